// round 17
// baseline (speedup 1.0000x reference)
#include <cuda_runtime.h>
#include <cuda_bf16.h>
#include <cuda_fp16.h>
#include <math.h>
#include <stdint.h>

// Problem dims
#define Bsz 8
#define Ssz 256
#define Vsz 32000
#define Dsz 512
#define Nly 16
#define Rsz 512
#define G4  2048            // 4*R
#define Mtok (Bsz*Ssz)      // 2048 tokens
#define NBR (Nly*Bsz*Rsz)   // 65536

// ---------------- scratch (static device globals; no runtime alloc) ----------
__device__ float g_X   [Mtok*Dsz];
__device__ float g_Gih [(size_t)Ssz*Nly*Bsz*G4];         // [t][n][b][g]
__device__ float g_hall[NBR];                            // final-step h only (hf)
__device__ float g_cf  [NBR];
__device__ float g_q   [Mtok*Dsz];
__device__ float g_ck  [Nly*Dsz];
__device__ float g_cv  [Nly*Dsz];
__device__ float g_k   [(size_t)Mtok*Nly*Dsz];
__device__ float g_v   [(size_t)Mtok*Nly*Dsz];
__device__ float g_att [Mtok*Dsz];
__device__ float g_mix [Mtok*Dsz];
__device__ unsigned g_bars[Nly];

// fp16 buffers
__device__ __align__(16) __half hWih   [(size_t)Nly*G4*Dsz];   // single
__device__ __align__(16) __half hWhh   [(size_t)Nly*G4*Dsz];   // single
__device__ __align__(16) __half hHead  [(size_t)Vsz*Dsz];      // single
__device__ __align__(16) __half hX_h   [Mtok*Dsz];
__device__ __align__(16) __half hX_l   [Mtok*Dsz];
__device__ __align__(16) __half hHall_h[(size_t)Ssz*NBR];
__device__ __align__(16) __half hHall_l[(size_t)Ssz*NBR];
__device__ __align__(16) __half hWnk   [Nly*Dsz*Rsz];          // single
__device__ __align__(16) __half hWnv   [Nly*Dsz*Rsz];          // single
__device__ __align__(16) __half hMix_h [Mtok*Dsz];
__device__ __align__(16) __half hMix_l [Mtok*Dsz];

__device__ __forceinline__ float sigm(float x){ return 1.f/(1.f+__expf(-x)); }

// ======================= PTX helpers (compute_103-safe) ======================
__device__ __forceinline__ void cp16(uint32_t sdst, const void* gsrc){
    asm volatile("cp.async.cg.shared.global [%0], [%1], 16;" :: "r"(sdst), "l"(gsrc));
}
__device__ __forceinline__ void cp_commit(){
    asm volatile("cp.async.commit_group;" ::: "memory");
}
template<int N>
__device__ __forceinline__ void cp_wait(){
    asm volatile("cp.async.wait_group %0;" :: "n"(N) : "memory");
}
__device__ __forceinline__ void ldsm_x4(uint32_t* r, uint32_t addr){
    asm volatile("ldmatrix.sync.aligned.m8n8.x4.shared.b16 {%0,%1,%2,%3}, [%4];"
        : "=r"(r[0]),"=r"(r[1]),"=r"(r[2]),"=r"(r[3]) : "r"(addr));
}
__device__ __forceinline__ void mma16816h(float* d, const uint32_t* a, const uint32_t* b){
    asm volatile("mma.sync.aligned.m16n8k16.row.col.f32.f16.f16.f32 "
        "{%0,%1,%2,%3}, {%4,%5,%6,%7}, {%8,%9}, {%0,%1,%2,%3};"
        : "+f"(d[0]),"+f"(d[1]),"+f"(d[2]),"+f"(d[3])
        : "r"(a[0]),"r"(a[1]),"r"(a[2]),"r"(a[3]), "r"(b[0]),"r"(b[1]));
}
__device__ __forceinline__ void bar_arrive_release(unsigned* p){
    asm volatile("red.release.gpu.global.add.u32 [%0], 1;" :: "l"(p) : "memory");
}
__device__ __forceinline__ unsigned ld_acquire(const unsigned* p){
    unsigned v;
    asm volatile("ld.acquire.gpu.global.u32 %0, [%1];" : "=r"(v) : "l"(p) : "memory");
    return v;
}

// ======================= mma.sync fp16 2-product GEMM ========================
// K-chunk 32, 2 stages, 61 KB smem -> 2 CTAs/SM so sync bubbles overlap.
#define TG_LD   40                 // 32 + 8 pad (halfs): ldsm bank-clean
#define TG_BLK  (128*TG_LD)        // 5120 halfs
#define TG_SMEM (2*3*TG_BLK*2)     // 61440 B

template<int MODE>
__global__ void __launch_bounds__(256,2) tgemm_k(
    const __half* __restrict__ Ah, const __half* __restrict__ Al,
    const __half* __restrict__ B,
    float* __restrict__ C, const float* __restrict__ bias,
    const float* __restrict__ bias2)
{
    extern __shared__ __align__(16) __half smb[];
    uint32_t sbase = (uint32_t)__cvta_generic_to_shared(smb);
    int tid = threadIdx.x, wid = tid>>5, lane = tid&31;
    int wm = wid>>2, wn = wid&3;
    int bn = blockIdx.x, bm = blockIdx.y, nz = blockIdx.z;

    const __half *BP = B;
    if (MODE==1) BP += (size_t)nz*G4 *512;
    if (MODE==3) BP += (size_t)nz*Dsz*512;

    int lrow = tid>>1, lk = (tid&1)*16;
    int am = bm*128 + lrow;
    int ag = (MODE==3) ? ((am>>3)*128 + nz*8 + (am&7)) : am;
    const __half* gAh = Ah + (size_t)ag*512 + lk;
    const __half* gAl = Al + (size_t)ag*512 + lk;
    const __half* gB  = BP + (size_t)(bn*128 + lrow)*512 + lk;
    uint32_t sRowOff = (uint32_t)(lrow*TG_LD + lk)*2;

    int aRowL = wm*64 + (lane&15);
    int aColL = (lane>>4)*8;
    int bRowL = wn*32 + ((lane>>4)&1)*8 + (lane&7);
    int bColL = ((lane>>3)&1)*8;

    float acc[4][4][4];
    #pragma unroll
    for (int i=0;i<4;i++){
        #pragma unroll
        for (int j=0;j<4;j++){
            acc[i][j][0]=0.f; acc[i][j][1]=0.f; acc[i][j][2]=0.f; acc[i][j][3]=0.f;
        }
    }

    auto issue = [&](int s, int kb){
        uint32_t d0 = sbase + (uint32_t)((s*3+0)*TG_BLK)*2 + sRowOff;
        uint32_t d1 = sbase + (uint32_t)((s*3+1)*TG_BLK)*2 + sRowOff;
        uint32_t d2 = sbase + (uint32_t)((s*3+2)*TG_BLK)*2 + sRowOff;
        #pragma unroll
        for (int i=0;i<2;i++){
            cp16(d0 + i*16, gAh + kb + i*8);
            cp16(d1 + i*16, gAl + kb + i*8);
            cp16(d2 + i*16, gB  + kb + i*8);
        }
        cp_commit();
    };

    issue(0, 0);
    for (int c=0;c<16;c++){
        int s = c&1;
        cp_wait<0>();
        __syncthreads();      // chunk c visible AND prev reads of stage s^1 done
        if (c<15) issue(s^1, (c+1)*32);

        #pragma unroll
        for (int ks=0; ks<2; ks++){
            int kc = ks*16;
            uint32_t ah[4][4], al[4][4];
            #pragma unroll
            for (int mf=0; mf<4; mf++){
                uint32_t addrh = sbase + (uint32_t)((s*3+0)*TG_BLK + (aRowL+mf*16)*TG_LD + aColL + kc)*2;
                uint32_t addrl = sbase + (uint32_t)((s*3+1)*TG_BLK + (aRowL+mf*16)*TG_LD + aColL + kc)*2;
                ldsm_x4(ah[mf], addrh);
                ldsm_x4(al[mf], addrl);
            }
            uint32_t bb[2][4];
            #pragma unroll
            for (int nfh=0; nfh<2; nfh++){
                uint32_t addrb = sbase + (uint32_t)((s*3+2)*TG_BLK + (bRowL+nfh*16)*TG_LD + bColL + kc)*2;
                ldsm_x4(bb[nfh], addrb);
            }
            #pragma unroll
            for (int mf=0; mf<4; mf++){
                #pragma unroll
                for (int nf=0; nf<4; nf++){
                    const uint32_t* bp = &bb[nf>>1][(nf&1)*2];
                    mma16816h(acc[mf][nf], ah[mf], bp);
                    mma16816h(acc[mf][nf], al[mf], bp);
                }
            }
        }
    }

    int rA = lane>>2, cA = (lane&3)*2;
    #pragma unroll
    for (int mf=0; mf<4; mf++){
        #pragma unroll
        for (int nf=0; nf<4; nf++){
            #pragma unroll
            for (int half=0; half<2; half++){
                int m  = bm*128 + wm*64 + mf*16 + rA + half*8;
                int jc = bn*128 + wn*32 + nf*8 + cA;
                float v0 = acc[mf][nf][half*2+0];
                float v1 = acc[mf][nf][half*2+1];
                if (MODE==1){
                    v0 += bias[nz*G4+jc]   + bias2[nz*G4+jc];
                    v1 += bias[nz*G4+jc+1] + bias2[nz*G4+jc+1];
                    int t=m>>3, b=m&7;
                    float2 w = {v0,v1};
                    *(float2*)&C[(size_t)(t*128+nz*8+b)*G4 + jc] = w;
                } else if (MODE==2){
                    v0 += bias[jc]; v1 += bias[jc+1];
                    int t=m>>3, b=m&7;
                    float2 w = {v0,v1};
                    *(float2*)&C[(size_t)(b*Ssz+t)*Vsz + jc] = w;
                } else {
                    v0 += bias[nz*Dsz+jc]; v1 += bias[nz*Dsz+jc+1];
                    float2 w = {v0,v1};
                    *(float2*)&C[(size_t)(m*Nly+nz)*Dsz + jc] = w;
                }
            }
        }
    }
}

// ---------------- fp32 -> fp16 single convert ---------------------------------
__global__ void __launch_bounds__(256) cvtH_k(const float* __restrict__ src,
                                              __half* __restrict__ dst, int n)
{
    int i = blockIdx.x*256 + threadIdx.x;
    if (i < n) dst[i] = __float2half(src[i]);
}

// ---------------- fused: embedding gather + fp16 split ------------------------
__global__ void __launch_bounds__(256) embed_split_k(const int* __restrict__ x,
                                                     const float* __restrict__ emb)
{
    int idx = blockIdx.x*256 + threadIdx.x;
    int m = idx>>9, d = idx&511;
    int t = m>>3, b = m&7;
    float v = emb[(size_t)x[b*Ssz+t]*Dsz + d];
    g_X[idx] = v;
    __half h = __float2half(v);
    hX_h[idx] = h;
    hX_l[idx] = __float2half(v - __half2float(h));
}

// ---------------- fused: Wih + Whh -> fp16 + zero layer barriers --------------
__global__ void __launch_bounds__(256) cvtW2_k(const float* __restrict__ s1,
                                               __half* __restrict__ d1,
                                               const float* __restrict__ s2,
                                               __half* __restrict__ d2,
                                               int n)
{
    int i = blockIdx.x*256 + threadIdx.x;
    if (i < Nly) g_bars[i] = 0u;
    if (i < n) d1[i] = __float2half(s1[i]);
    else       d2[i - n] = __float2half(s2[i - n]);
}

// ---------------- SIMT 128x128 GEMM (modes 0,4: fp32 C ; 5: fp16 C) ----------
template<int MODE>
__global__ void __launch_bounds__(256, 2) gemm_k(
    const float* __restrict__ A, const float* __restrict__ Bw,
    float* __restrict__ C, __half* __restrict__ Ch,
    const float* __restrict__ bias, const float* __restrict__ resid)
{
    const int K = 512;
    __shared__ float As[2][8][132];
    __shared__ float Bs[2][8][132];
    int tid = threadIdx.x;
    int bn = blockIdx.x, bm = blockIdx.y, n = blockIdx.z;

    const float* Bp = Bw;
    if (MODE==5) Bp += (size_t)n*Dsz*Rsz;

    int lRow = tid>>1, lK = (tid&1)<<2;
    const float* Aptr = A + (size_t)(bm*128+lRow)*K + lK;
    const float* Bptr;
    int b_k=0, b_j=0;
    if (MODE==5){
        b_k = tid>>5; b_j = (tid&31)<<2;
        Bptr = Bp + (size_t)b_k*Rsz + bn*128 + b_j;
    } else {
        Bptr = Bp + (size_t)(bn*128 + lRow)*K + lK;
    }
    int ty = tid>>4, tx = tid&15;
    float acc[8][8] = {};
    float4 aReg, bReg;

    aReg = *(const float4*)(Aptr);
    bReg = *(const float4*)(Bptr);
    As[0][lK+0][lRow]=aReg.x; As[0][lK+1][lRow]=aReg.y;
    As[0][lK+2][lRow]=aReg.z; As[0][lK+3][lRow]=aReg.w;
    if (MODE==5){ *(float4*)&Bs[0][b_k][b_j] = bReg; }
    else {
        Bs[0][lK+0][lRow]=bReg.x; Bs[0][lK+1][lRow]=bReg.y;
        Bs[0][lK+2][lRow]=bReg.z; Bs[0][lK+3][lRow]=bReg.w;
    }
    __syncthreads();

    int buf = 0;
    for (int kb=8; kb<=K; kb+=8){
        bool more = (kb < K);
        if (more){
            aReg = *(const float4*)(Aptr + kb);
            bReg = (MODE==5) ? *(const float4*)(Bptr + (size_t)kb*Rsz)
                             : *(const float4*)(Bptr + kb);
        }
        #pragma unroll
        for (int k=0;k<8;k++){
            float4 a0 = *(const float4*)&As[buf][k][ty<<2];
            float4 a1 = *(const float4*)&As[buf][k][(ty<<2)+64];
            float4 b0 = *(const float4*)&Bs[buf][k][tx<<2];
            float4 b1 = *(const float4*)&Bs[buf][k][(tx<<2)+64];
            float a[8]={a0.x,a0.y,a0.z,a0.w,a1.x,a1.y,a1.z,a1.w};
            float b[8]={b0.x,b0.y,b0.z,b0.w,b1.x,b1.y,b1.z,b1.w};
            #pragma unroll
            for(int i=0;i<8;i++)
                #pragma unroll
                for(int j=0;j<8;j++) acc[i][j] += a[i]*b[j];
        }
        if (more){
            int nb = buf^1;
            As[nb][lK+0][lRow]=aReg.x; As[nb][lK+1][lRow]=aReg.y;
            As[nb][lK+2][lRow]=aReg.z; As[nb][lK+3][lRow]=aReg.w;
            if (MODE==5){ *(float4*)&Bs[nb][b_k][b_j] = bReg; }
            else {
                Bs[nb][lK+0][lRow]=bReg.x; Bs[nb][lK+1][lRow]=bReg.y;
                Bs[nb][lK+2][lRow]=bReg.z; Bs[nb][lK+3][lRow]=bReg.w;
            }
            __syncthreads();
            buf = nb;
        }
    }

    #pragma unroll
    for(int i=0;i<8;i++){
        int m = bm*128 + (ty<<2) + (i&3) + ((i>>2)<<6);
        #pragma unroll
        for(int j=0;j<8;j++){
            int jc = bn*128 + (tx<<2) + (j&3) + ((j>>2)<<6);
            float v = acc[i][j];
            if (MODE==0){ v += bias[jc]; C[(size_t)m*Dsz+jc]=v; }
            else if (MODE==4){ v += bias[jc] + resid[(size_t)m*Dsz+jc]; C[(size_t)m*Dsz+jc]=v; }
            else { Ch[(size_t)n*Dsz*Rsz + (size_t)m*Rsz + jc] = __float2half(v); }
        }
    }
}

// ---------------- combined k/v biases ----------------------------------------
__global__ void __launch_bounds__(256) ckcv_k(const float* __restrict__ in_w,
                                              const float* __restrict__ in_b,
                                              const float* __restrict__ b_np)
{
    int idx = blockIdx.x*256 + threadIdx.x;
    int n = idx>>9, dc = idx&511;
    const float* Wk = in_w + Dsz*Dsz;
    const float* Wv = in_w + 2*Dsz*Dsz;
    const float* bn = b_np + n*Dsz;
    float sk = in_b[Dsz+dc], sv = in_b[2*Dsz+dc];
    for (int j=0;j<Dsz;j++){
        float bj = bn[j];
        sk += Wk[(size_t)dc*Dsz+j]*bj;
        sv += Wv[(size_t)dc*Dsz+j]*bj;
    }
    g_ck[idx]=sk; g_cv[idx]=sv;
}

// ---------------- persistent LSTM: resident-W half + warp specialization -----
#define LSWR 520
#define L_OFF_WRES 0
#define L_SZ_WRES  (128*LSWR*2)
#define LSW  40
#define L_WSBLK2 (128*LSW)
#define L_OFF_WS   L_SZ_WRES
#define L_SZ_WS    (4*L_WSBLK2*2)
#define LSH 536
#define L_OFF_HH (L_OFF_WS + L_SZ_WS)
#define L_OFF_HL (L_OFF_HH + 8*LSH*2)
#define L_OFF_GA (L_OFF_HL + 8*LSH*2)
#define L_OFF_CS (L_OFF_GA + 256*9*4)
#define L_OFF_GT (L_OFF_CS + 64*9*4)
#define L_SMEM   (L_OFF_GT + 8192)

__global__ void __launch_bounds__(256,1) lstm_mma(
    const __half* __restrict__ W,
    const float* __restrict__ h0, const float* __restrict__ c0,
    float* __restrict__ hfinal,
    __half* __restrict__ hall_h, __half* __restrict__ hall_l,
    const float* __restrict__ Gih, float* __restrict__ cfinal)
{
    extern __shared__ __align__(16) char sm[];
    uint32_t sbase = (uint32_t)__cvta_generic_to_shared(sm);
    __half* hh_s = (__half*)(sm + L_OFF_HH);
    __half* hl_s = (__half*)(sm + L_OFF_HL);
    float* ga  = (float*)(sm + L_OFF_GA);
    float* cs  = (float*)(sm + L_OFF_CS);
    float* gts = (float*)(sm + L_OFF_GT);

    int tid = threadIdx.x, wid = tid>>5, lane = tid&31;
    int chunk = blockIdx.x & 7, n = blockIdx.x >> 3;

    const __half* Wbase = W + (size_t)n*G4*512;

    for (int idx=tid; idx<512; idx+=256){
        int b = idx>>6, r = idx&63;
        cs[r*9+b] = c0[(size_t)(n*8+b)*Rsz + chunk*64 + r];
    }

    int aRow = lane&15, aCol = (lane>>4)*8;
    int bN = lane>>2, bK2 = 2*(lane&3);

    int j = tid - 128;
    const __half* gWs = nullptr;
    if (tid >= 128){
        int m = 128 + j;
        gWs = Wbase + (size_t)((m>>6)*512 + chunk*64 + (m&63))*512;
    }
    auto issueS = [&](int kc, int s){
        uint32_t dw = sbase + L_OFF_WS + (uint32_t)(s*L_WSBLK2 + j*LSW)*2;
        const __half* sw = gWs + kc*32;
        #pragma unroll
        for (int i=0;i<4;i++) cp16(dw + i*16, sw + i*8);
        cp_commit();
    };
    auto issueGt = [&](int t){
        const float* GtBase = Gih + (size_t)t*Nly*Bsz*G4 + (size_t)(n*8)*G4 + chunk*64;
        #pragma unroll
        for (int jj=0; jj<4; jj++){
            int idx = tid + jj*128;
            int b = idx>>6, gate = (idx>>4)&3, quad = idx&15;
            cp16(sbase + L_OFF_GT + (uint32_t)idx*16,
                 GtBase + (size_t)b*G4 + gate*512 + quad*4);
        }
        cp_commit();
    };

    // ---- one-time: resident W rows 0..127 into smem ----
    {
        int row = tid>>1, half = tid&1;
        const __half* gsrc = Wbase + (size_t)((row>>6)*512 + chunk*64 + (row&63))*512 + half*256;
        uint32_t dst = sbase + L_OFF_WRES + (uint32_t)(row*LSWR + half*256)*2;
        #pragma unroll
        for (int i=0;i<32;i++) cp16(dst + i*16, gsrc + i*8);
        cp_commit();
    }
    if (tid < 128){ issueGt(0); cp_wait<1>(); }
    else { issueS(0,0); issueS(1,1); issueS(2,2); cp_wait<3>(); }
    __syncthreads();

    for (int t=0; t<Ssz; t++){
        // ---- load h (prev) into smem fp16 hi/lo ----
        if (t==0){
            for (int idx=tid; idx<4096; idx+=256){
                int b = idx>>9, r = idx&511;
                float v = h0[(size_t)(n*8+b)*Rsz + r];
                __half hh = __float2half(v);
                hh_s[b*LSH + r] = hh;
                hl_s[b*LSH + r] = __float2half(v - __half2float(hh));
            }
        } else {
            const __half* ph = hall_h + (size_t)(t-1)*NBR + (size_t)(n*8)*Rsz;
            const __half* pl = hall_l + (size_t)(t-1)*NBR + (size_t)(n*8)*Rsz;
            for (int idx=tid; idx<512; idx+=256){
                int b = idx>>6, r8 = (idx&63)*8;
                *(uint4*)(hh_s + b*LSH + r8) = *(const uint4*)(ph + b*Rsz + r8);
                *(uint4*)(hl_s + b*LSH + r8) = *(const uint4*)(pl + b*Rsz + r8);
            }
        }
        __syncthreads();

        float acc[2][4];
        #pragma unroll
        for (int f=0;f<2;f++){ acc[f][0]=0.f; acc[f][1]=0.f; acc[f][2]=0.f; acc[f][3]=0.f; }

        if (tid < 128){
            // resident warps 0-3: no syncs
            for (int kc=0; kc<16; kc++){
                #pragma unroll
                for (int kf=0; kf<2; kf++){
                    int kbase = kc*32 + kf*16;
                    uint32_t bhr[2], blr[2];
                    uint32_t hoff = (uint32_t)(bN*LSH + kbase + bK2)*2;
                    bhr[0] = *(const uint32_t*)(sm + L_OFF_HH + hoff);
                    bhr[1] = *(const uint32_t*)(sm + L_OFF_HH + hoff + 16);
                    blr[0] = *(const uint32_t*)(sm + L_OFF_HL + hoff);
                    blr[1] = *(const uint32_t*)(sm + L_OFF_HL + hoff + 16);
                    #pragma unroll
                    for (int f=0; f<2; f++){
                        uint32_t aw[4];
                        uint32_t wadr = sbase + L_OFF_WRES +
                            (uint32_t)((wid*32 + f*16 + aRow)*LSWR + kbase + aCol)*2;
                        ldsm_x4(aw, wadr);
                        mma16816h(acc[f], aw, bhr);
                        mma16816h(acc[f], aw, blr);
                    }
                }
            }
            cp_wait<0>();   // Gt(t) done
        } else {
            // streamed warps 4-7: private pipeline
            int wl = wid - 4;
            for (int kc=0; kc<16; kc++){
                int s = kc&3;
                if      (kc<=13) cp_wait<2>();
                else if (kc==14) cp_wait<1>();
                else             cp_wait<0>();
                asm volatile("bar.sync 1, 128;" ::: "memory");
                if (kc+3 < 16) issueS(kc+3, (kc+3)&3);
                #pragma unroll
                for (int kf=0; kf<2; kf++){
                    int kbase = kc*32 + kf*16;
                    uint32_t bhr[2], blr[2];
                    uint32_t hoff = (uint32_t)(bN*LSH + kbase + bK2)*2;
                    bhr[0] = *(const uint32_t*)(sm + L_OFF_HH + hoff);
                    bhr[1] = *(const uint32_t*)(sm + L_OFF_HH + hoff + 16);
                    blr[0] = *(const uint32_t*)(sm + L_OFF_HL + hoff);
                    blr[1] = *(const uint32_t*)(sm + L_OFF_HL + hoff + 16);
                    #pragma unroll
                    for (int f=0; f<2; f++){
                        uint32_t aw[4];
                        uint32_t wadr = sbase + L_OFF_WS +
                            (uint32_t)(s*L_WSBLK2 + (wl*32 + f*16 + aRow)*LSW + kf*16 + aCol)*2;
                        ldsm_x4(aw, wadr);
                        mma16816h(acc[f], aw, bhr);
                        mma16816h(acc[f], aw, blr);
                    }
                }
            }
        }

        // ---- gates to smem ----
        int rA = lane>>2, cB = 2*(lane&3);
        #pragma unroll
        for (int f=0; f<2; f++){
            int m = wid*32 + f*16 + rA;
            ga[m*9 + cB]       = acc[f][0];
            ga[m*9 + cB + 1]   = acc[f][1];
            ga[(m+8)*9 + cB]   = acc[f][2];
            ga[(m+8)*9 + cB+1] = acc[f][3];
        }
        __syncthreads();

        // ---- elementwise LSTM + h split writeback ----
        for (int idx=tid; idx<512; idx+=256){
            int b = idx>>6, r = idx&63;
            float iv = ga[(      r)*9 + b] + gts[b*256       + r];
            float fv = ga[( 64 + r)*9 + b] + gts[b*256 +  64 + r];
            float gv = ga[(128 + r)*9 + b] + gts[b*256 + 128 + r];
            float ov = ga[(192 + r)*9 + b] + gts[b*256 + 192 + r];
            float cp = cs[r*9+b];
            float cn = sigm(fv)*cp + sigm(iv)*tanhf(gv);
            cs[r*9+b] = cn;
            float hv = sigm(ov)*tanhf(cn);
            size_t ho = (size_t)t*NBR + (size_t)(n*8+b)*Rsz + chunk*64 + r;
            __half hh = __float2half(hv);
            hall_h[ho] = hh;
            hall_l[ho] = __float2half(hv - __half2float(hh));
            if (t == Ssz-1)
                hfinal[(size_t)(n*8+b)*Rsz + chunk*64 + r] = hv;
        }
        __syncthreads();

        if (t+1 < Ssz){
            if (tid < 128) issueGt(t+1);
            else { issueS(0,0); issueS(1,1); issueS(2,2); }
            if (tid==0){
                bar_arrive_release(&g_bars[n]);
                unsigned target = 8u*(unsigned)(t+1);
                while (ld_acquire(&g_bars[n]) < target) { }
            }
            __syncthreads();
        }
    }

    for (int idx=tid; idx<512; idx+=256){
        int b = idx>>6, r = idx&63;
        cfinal[(size_t)(n*8+b)*Rsz + chunk*64 + r] = cs[r*9+b];
    }
}

// ---------------- attention per token ----------------------------------------
__global__ void __launch_bounds__(256) attn_k()
{
    int m = blockIdx.x, tid = threadIdx.x;
    __shared__ float sq[512];
    __shared__ float sc[8][16];
    __shared__ float sw[8][16];
    sq[tid]     = g_q[(size_t)m*Dsz + tid];
    sq[tid+256] = g_q[(size_t)m*Dsz + tid + 256];
    __syncthreads();
    if (tid < 128){
        int h = tid>>4, nn = tid&15;
        const float* kp = g_k + (size_t)(m*Nly+nn)*Dsz + h*64;
        float s = 0.f;
        #pragma unroll 8
        for (int e=0;e<64;e++) s += sq[h*64+e]*kp[e];
        sc[h][nn] = s*0.125f;
    }
    __syncthreads();
    if (tid < 8){
        float mx = -1e30f;
        for (int nn=0;nn<16;nn++) mx = fmaxf(mx, sc[tid][nn]);
        float e[16], sum = 0.f;
        for (int nn=0;nn<16;nn++){ e[nn]=expf(sc[tid][nn]-mx); sum+=e[nn]; }
        float inv = 1.f/sum;
        for (int nn=0;nn<16;nn++) sw[tid][nn]=e[nn]*inv;
    }
    __syncthreads();
    for (int idx=tid; idx<512; idx+=256){
        int h = idx>>6;
        float s = 0.f;
        #pragma unroll
        for (int nn=0;nn<16;nn++)
            s += sw[h][nn]*g_v[(size_t)(m*Nly+nn)*Dsz + idx];
        g_att[(size_t)m*Dsz + idx] = s;
    }
}

// ---------------- layernorm + fp16 hi/lo split (fused) ------------------------
__global__ void __launch_bounds__(256) ln_k(const float* __restrict__ gam,
                                            const float* __restrict__ bet)
{
    int m = blockIdx.x, tid = threadIdx.x;
    __shared__ float sh[8];
    __shared__ float sh2[8];
    float* row = g_mix + (size_t)m*Dsz;
    float v0 = row[tid], v1 = row[tid+256];
    int lane = tid&31, w = tid>>5;

    float s = v0+v1;
    #pragma unroll
    for (int o=16;o>0;o>>=1) s += __shfl_xor_sync(0xffffffffu, s, o);
    if (lane==0) sh[w]=s;
    __syncthreads();
    float tot = sh[0]+sh[1]+sh[2]+sh[3]+sh[4]+sh[5]+sh[6]+sh[7];
    float mu = tot*(1.f/512.f);

    float d0=v0-mu, d1=v1-mu;
    float s2 = d0*d0+d1*d1;
    #pragma unroll
    for (int o=16;o>0;o>>=1) s2 += __shfl_xor_sync(0xffffffffu, s2, o);
    if (lane==0) sh2[w]=s2;
    __syncthreads();
    float tot2 = sh2[0]+sh2[1]+sh2[2]+sh2[3]+sh2[4]+sh2[5]+sh2[6]+sh2[7];
    float inv = rsqrtf(tot2*(1.f/512.f) + 1e-5f);

    float r0 = d0*inv*gam[tid]     + bet[tid];
    float r1 = d1*inv*gam[tid+256] + bet[tid+256];
    size_t o0 = (size_t)m*Dsz + tid, o1 = o0 + 256;
    __half h0 = __float2half(r0), h1 = __float2half(r1);
    hMix_h[o0] = h0; hMix_l[o0] = __float2half(r0 - __half2float(h0));
    hMix_h[o1] = h1; hMix_l[o1] = __float2half(r1 - __half2float(h1));
}

// ---------------- final state copy ------------------------------------------
__global__ void __launch_bounds__(256) copyhc_k(const float* __restrict__ hf,
                                                const float* __restrict__ cf,
                                                float* __restrict__ out)
{
    int idx = blockIdx.x*256 + threadIdx.x;
    const size_t L = (size_t)Bsz*Ssz*Vsz;
    out[L + idx]       = hf[idx];
    out[L + NBR + idx] = cf[idx];
}

// =============================================================================
extern "C" void kernel_launch(void* const* d_in, const int* in_sizes, int n_in,
                              void* d_out, int out_size)
{
    const int*   x      = (const int*)  d_in[0];
    const float* h0     = (const float*)d_in[1];
    const float* c0     = (const float*)d_in[2];
    const float* emb    = (const float*)d_in[3];
    const float* W_ih   = (const float*)d_in[4];
    const float* b_ih   = (const float*)d_in[5];
    const float* W_hh   = (const float*)d_in[6];
    const float* b_hh   = (const float*)d_in[7];
    const float* W_np   = (const float*)d_in[8];
    const float* b_np   = (const float*)d_in[9];
    const float* in_w   = (const float*)d_in[10];
    const float* in_b   = (const float*)d_in[11];
    const float* op_w   = (const float*)d_in[12];
    const float* op_b   = (const float*)d_in[13];
    const float* ln_g   = (const float*)d_in[14];
    const float* ln_b   = (const float*)d_in[15];
    const float* head_w = (const float*)d_in[16];
    const float* head_b = (const float*)d_in[17];
    float* out = (float*)d_out;

    cudaFuncSetAttribute(tgemm_k<1>, cudaFuncAttributeMaxDynamicSharedMemorySize, TG_SMEM);
    cudaFuncSetAttribute(tgemm_k<2>, cudaFuncAttributeMaxDynamicSharedMemorySize, TG_SMEM);
    cudaFuncSetAttribute(tgemm_k<3>, cudaFuncAttributeMaxDynamicSharedMemorySize, TG_SMEM);
    cudaFuncSetAttribute(lstm_mma,   cudaFuncAttributeMaxDynamicSharedMemorySize, L_SMEM);

    float *pX,*pGih,*pHall,*pCf,*pQ,*pCk,*pCv,*pK,*pV,*pAtt,*pMix;
    __half *pWih,*pWhh,*pHead,*pXH,*pXL,*pHallH,*pHallL,*pWnkH,*pWnvH,*pMixH,*pMixL;
    cudaGetSymbolAddress((void**)&pX,    g_X);
    cudaGetSymbolAddress((void**)&pGih,  g_Gih);
    cudaGetSymbolAddress((void**)&pHall, g_hall);
    cudaGetSymbolAddress((void**)&pCf,   g_cf);
    cudaGetSymbolAddress((void**)&pQ,    g_q);
    cudaGetSymbolAddress((void**)&pCk,   g_ck);
    cudaGetSymbolAddress((void**)&pCv,   g_cv);
    cudaGetSymbolAddress((void**)&pK,    g_k);
    cudaGetSymbolAddress((void**)&pV,    g_v);
    cudaGetSymbolAddress((void**)&pAtt,  g_att);
    cudaGetSymbolAddress((void**)&pMix,  g_mix);
    cudaGetSymbolAddress((void**)&pWih,  hWih);
    cudaGetSymbolAddress((void**)&pWhh,  hWhh);
    cudaGetSymbolAddress((void**)&pHead, hHead);
    cudaGetSymbolAddress((void**)&pXH,   hX_h);    cudaGetSymbolAddress((void**)&pXL, hX_l);
    cudaGetSymbolAddress((void**)&pHallH,hHall_h); cudaGetSymbolAddress((void**)&pHallL,hHall_l);
    cudaGetSymbolAddress((void**)&pWnkH, hWnk);
    cudaGetSymbolAddress((void**)&pWnvH, hWnv);
    cudaGetSymbolAddress((void**)&pMixH, hMix_h);  cudaGetSymbolAddress((void**)&pMixL, hMix_l);

    // Launch order: index 3 = tgemm_k<1> (ncu captures 4th launch)
    embed_split_k<<<(Mtok*Dsz)/256, 256>>>(x, emb);                              // 0
    cvtW2_k<<<2*(Nly*G4*Dsz)/256,256>>>(W_ih,pWih, W_hh,pWhh, Nly*G4*Dsz);       // 1 (+bars=0)
    cvtH_k<<<(Vsz*Dsz)/256,256>>>(head_w, pHead, Vsz*Dsz);                       // 2
    tgemm_k<1><<<dim3(16,16,16),256,TG_SMEM>>>(pXH,pXL,pWih,pGih,b_ih,b_hh);     // 3 <- profiled
    lstm_mma<<<128,256,L_SMEM>>>(pWhh, h0, c0, pHall, pHallH, pHallL, pGih, pCf);// 4

    // Phase 1 remainder + Phase 3
    gemm_k<0><<<dim3(4,16),256>>>(pX, in_w, pQ, nullptr, in_b, nullptr);
    gemm_k<5><<<dim3(4,4,16),256>>>(in_w +   Dsz*Dsz, W_np, nullptr, pWnkH, nullptr, nullptr);
    gemm_k<5><<<dim3(4,4,16),256>>>(in_w + 2*Dsz*Dsz, W_np, nullptr, pWnvH, nullptr, nullptr);
    ckcv_k<<<(Nly*Dsz)/256, 256>>>(in_w, in_b, b_np);
    tgemm_k<3><<<dim3(4,16,16),256,TG_SMEM>>>(pHallH,pHallL,pWnkH,pK,pCk,nullptr);
    tgemm_k<3><<<dim3(4,16,16),256,TG_SMEM>>>(pHallH,pHallL,pWnvH,pV,pCv,nullptr);
    attn_k<<<Mtok,256>>>();
    gemm_k<4><<<dim3(4,16),256>>>(pAtt, op_w, pMix, nullptr, op_b, pX);
    ln_k<<<Mtok,256>>>(ln_g, ln_b);
    tgemm_k<2><<<dim3(250,16),256,TG_SMEM>>>(pMixH,pMixL,pHead,out,head_b,nullptr);

    // hf / cf
    copyhc_k<<<NBR/256,256>>>(pHall, pCf, out);
}